// round 3
// baseline (speedup 1.0000x reference)
#include <cuda_runtime.h>
#include <cuda_bf16.h>

// Problem constants (fixed shapes for this problem instance)
#define NMAX 100000
#define EMAX 6400000
#define HID  256
#define OUT  64
#define NT   32      // nodes per MLP tile

// Scratch (device globals: no allocation allowed in kernel_launch)
__device__ float g_xl[NMAX * 4];    // stride 4, 16B rows
__device__ float g_h1[NMAX * 16];   // stride 16, 64B rows (2 sectors per gather)
__device__ float g_h2[NMAX * 28];   // stride 28
__device__ int    g_count[NMAX];
__device__ int    g_off[NMAX + 1];
__device__ int    g_cursor[NMAX];
__device__ float4 g_edges[EMAX];    // {src(as int bits), k0, k1, k2} sorted by dst

// ---------------------------------------------------------------------------
// zero per-launch state (only the histogram counters now)
// ---------------------------------------------------------------------------
__global__ void zero_kernel(int N) {
    int i = blockIdx.x * blockDim.x + threadIdx.x;
    if (i < N) g_count[i] = 0;
}

// ---------------------------------------------------------------------------
// xl[n,i] = sum_j gauges[n,j,i] * x[n,j]
// ---------------------------------------------------------------------------
__global__ void xl_kernel(const float* __restrict__ x,
                          const float* __restrict__ g, int N) {
    int n = blockIdx.x * blockDim.x + threadIdx.x;
    if (n >= N) return;
    float x0 = x[n * 3 + 0], x1 = x[n * 3 + 1], x2 = x[n * 3 + 2];
    const float* G = g + n * 9;
    float o0 = x0 * G[0] + x1 * G[3] + x2 * G[6];
    float o1 = x0 * G[1] + x1 * G[4] + x2 * G[7];
    float o2 = x0 * G[2] + x1 * G[5] + x2 * G[8];
    ((float4*)g_xl)[n] = make_float4(o0, o1, o2, 0.f);
}

// ---------------------------------------------------------------------------
// CSR build: histogram by dst
// ---------------------------------------------------------------------------
__global__ void hist_kernel(const int* __restrict__ ei, int E) {
    int e = blockIdx.x * blockDim.x + threadIdx.x;
    if (e >= E) return;
    atomicAdd(&g_count[ei[E + e]], 1);
}

// ---------------------------------------------------------------------------
// Exclusive scan over g_count -> g_off, g_cursor. One block, 1024 threads.
// ---------------------------------------------------------------------------
__global__ __launch_bounds__(1024) void scan_kernel(int N, int E) {
    const int C = (NMAX + 1023) / 1024;   // 98 elements per thread
    __shared__ int sm[1024];
    int t = threadIdx.x;
    int base = t * C;

    int mysum = 0;
    for (int i = 0; i < C; i++) {
        int idx = base + i;
        if (idx < N) mysum += g_count[idx];
    }
    sm[t] = mysum;
    __syncthreads();
    // Hillis-Steele inclusive scan
    for (int off = 1; off < 1024; off <<= 1) {
        int v = (t >= off) ? sm[t - off] : 0;
        __syncthreads();
        sm[t] += v;
        __syncthreads();
    }
    int run = sm[t] - mysum;   // exclusive prefix for this thread's chunk
    for (int i = 0; i < C; i++) {
        int idx = base + i;
        if (idx < N) {
            g_off[idx]    = run;
            g_cursor[idx] = run;
            run += g_count[idx];
        }
    }
    if (t == 1023) g_off[N] = E;
}

// ---------------------------------------------------------------------------
// Place edges into CSR slots: record = {src, k0, k1, k2}
// ---------------------------------------------------------------------------
__global__ void place_kernel(const int* __restrict__ ei,
                             const float* __restrict__ K, int E) {
    int e = blockIdx.x * blockDim.x + threadIdx.x;
    if (e >= E) return;
    int s = ei[e];
    int d = ei[E + e];
    float k0 = K[e], k1 = K[E + e], k2 = K[2 * E + e];
    int p = atomicAdd(&g_cursor[d], 1);
    g_edges[p] = make_float4(__int_as_float(s), k0, k1, k2);
}

// ---------------------------------------------------------------------------
// conv1 gather: h1[n, c*3+k] = sum_{e in csr(n)} K[k,e] * xl[src(e), c]
// one thread per node
// ---------------------------------------------------------------------------
__global__ void conv1_gather(int N) {
    int n = blockIdx.x * blockDim.x + threadIdx.x;
    if (n >= N) return;
    int b = g_off[n], en = g_off[n + 1];
    float a0 = 0, a1 = 0, a2 = 0, a3 = 0, a4 = 0, a5 = 0, a6 = 0, a7 = 0, a8 = 0;
    for (int i = b; i < en; i++) {
        float4 r = g_edges[i];
        int s = __float_as_int(r.x);
        float4 xv = ((const float4*)g_xl)[s];
        a0 += r.y * xv.x; a1 += r.z * xv.x; a2 += r.w * xv.x;
        a3 += r.y * xv.y; a4 += r.z * xv.y; a5 += r.w * xv.y;
        a6 += r.y * xv.z; a7 += r.z * xv.z; a8 += r.w * xv.z;
    }
    float4* row = (float4*)(g_h1 + n * 16);
    row[0] = make_float4(a0, a1, a2, a3);
    row[1] = make_float4(a4, a5, a6, a7);
    row[2] = make_float4(a8, 0.f, 0.f, 0.f);
}

// ---------------------------------------------------------------------------
// conv2 gather: h2[n, c*3+k] = sum_{e in csr(n)} K[k,e] * h1[src(e), c], c in [0,9)
// ---------------------------------------------------------------------------
__global__ void conv2_gather(int N) {
    int n = blockIdx.x * blockDim.x + threadIdx.x;
    if (n >= N) return;
    int b = g_off[n], en = g_off[n + 1];
    float acc[27];
#pragma unroll
    for (int i = 0; i < 27; i++) acc[i] = 0.f;
    for (int i = b; i < en; i++) {
        float4 r = g_edges[i];
        int s = __float_as_int(r.x);
        const float4* h1r = (const float4*)(g_h1 + s * 16);
        float4 A = h1r[0], B = h1r[1], C = h1r[2];
        float a[9] = {A.x, A.y, A.z, A.w, B.x, B.y, B.z, B.w, C.x};
#pragma unroll
        for (int c = 0; c < 9; c++) {
            acc[3 * c + 0] += r.y * a[c];
            acc[3 * c + 1] += r.z * a[c];
            acc[3 * c + 2] += r.w * a[c];
        }
    }
    float* row = g_h2 + n * 28;
#pragma unroll
    for (int q = 0; q < 6; q++)
        ((float4*)row)[q] = make_float4(acc[4 * q], acc[4 * q + 1], acc[4 * q + 2], acc[4 * q + 3]);
    ((float4*)row)[6] = make_float4(acc[24], acc[25], acc[26], 0.f);
}

// ---------------------------------------------------------------------------
// MLP: feats[39] = [xl(3) | h1(9) | h2(27)];  relu(feats@W1+b1)@W2+b2 -> out[64]
// ---------------------------------------------------------------------------
__global__ __launch_bounds__(256) void mlp_kernel(
    const float* __restrict__ W1, const float* __restrict__ b1,
    const float* __restrict__ W2, const float* __restrict__ b2,
    float* __restrict__ out, int N) {
    __shared__ float sh_feats[39 * NT];        // [j][n]
    __shared__ float sh_hmid[HID * 36];        // [h][n], stride 36

    int t = threadIdx.x;
    int node0 = blockIdx.x * NT;

    // --- load feats (transposed) ---
    {
        int n = t & (NT - 1);
        int node = node0 + n;
        bool valid = node < N;
        for (int j = t >> 5; j < 39; j += 8) {
            float v = 0.f;
            if (valid) {
                if (j < 3)       v = g_xl[node * 4 + j];
                else if (j < 12) v = g_h1[node * 16 + (j - 3)];
                else             v = g_h2[node * 28 + (j - 12)];
            }
            sh_feats[j * NT + n] = v;
        }
    }
    __syncthreads();

    // --- layer 1: hid[t][n] for n in [0,32) ---
    float acc[NT];
#pragma unroll
    for (int n = 0; n < NT; n++) acc[n] = 0.f;

    for (int j = 0; j < 39; j++) {
        float w = __ldg(W1 + j * HID + t);
        const float4* f4 = (const float4*)(sh_feats + j * NT);
#pragma unroll
        for (int q = 0; q < NT / 4; q++) {
            float4 f = f4[q];
            acc[4 * q + 0] += f.x * w;
            acc[4 * q + 1] += f.y * w;
            acc[4 * q + 2] += f.z * w;
            acc[4 * q + 3] += f.w * w;
        }
    }
    {
        float bb = __ldg(b1 + t);
        float* hr = sh_hmid + t * 36;
#pragma unroll
        for (int n = 0; n < NT; n++) hr[n] = fmaxf(acc[n] + bb, 0.f);
    }
    __syncthreads();

    // --- layer 2: 4 nodes x 2 outputs per thread ---
    int ng = t & 7;
    int og = t >> 3;
    int nb = 4 * ng;
    int o0 = 2 * og;
    float a00 = 0, a01 = 0, a10 = 0, a11 = 0, a20 = 0, a21 = 0, a30 = 0, a31 = 0;
#pragma unroll 4
    for (int h = 0; h < HID; h++) {
        float4 hm = *(const float4*)(sh_hmid + h * 36 + nb);
        float2 w = __ldg((const float2*)(W2 + h * OUT + o0));
        a00 += hm.x * w.x; a01 += hm.x * w.y;
        a10 += hm.y * w.x; a11 += hm.y * w.y;
        a20 += hm.z * w.x; a21 += hm.z * w.y;
        a30 += hm.w * w.x; a31 += hm.w * w.y;
    }
    float bo0 = __ldg(b2 + o0), bo1 = __ldg(b2 + o0 + 1);
    int node = node0 + nb;
    if (node + 0 < N) *(float2*)(out + (node + 0) * OUT + o0) = make_float2(a00 + bo0, a01 + bo1);
    if (node + 1 < N) *(float2*)(out + (node + 1) * OUT + o0) = make_float2(a10 + bo0, a11 + bo1);
    if (node + 2 < N) *(float2*)(out + (node + 2) * OUT + o0) = make_float2(a20 + bo0, a21 + bo1);
    if (node + 3 < N) *(float2*)(out + (node + 3) * OUT + o0) = make_float2(a30 + bo0, a31 + bo1);
}

// ---------------------------------------------------------------------------
// Launch: zero -> xl -> hist -> scan -> place -> conv1 -> conv2 -> mlp
// Inputs (metadata order): x, gauges, kernel_vals, W1, b1, W2, b2, edge_index
// ---------------------------------------------------------------------------
extern "C" void kernel_launch(void* const* d_in, const int* in_sizes, int n_in,
                              void* d_out, int out_size) {
    const float* x      = (const float*)d_in[0];
    const float* gauges = (const float*)d_in[1];
    const float* kvals  = (const float*)d_in[2];
    const float* W1     = (const float*)d_in[3];
    const float* b1     = (const float*)d_in[4];
    const float* W2     = (const float*)d_in[5];
    const float* b2     = (const float*)d_in[6];
    const int*   ei     = (const int*)d_in[7];   // int32 (JAX x64 disabled)
    float* out = (float*)d_out;

    int N = in_sizes[0] / 3;       // 100000
    int E = in_sizes[2] / 3;       // 6400000

    zero_kernel<<<(N + 255) / 256, 256>>>(N);
    xl_kernel<<<(N + 255) / 256, 256>>>(x, gauges, N);
    hist_kernel<<<(E + 255) / 256, 256>>>(ei, E);
    scan_kernel<<<1, 1024>>>(N, E);
    place_kernel<<<(E + 255) / 256, 256>>>(ei, kvals, E);
    conv1_gather<<<(N + 255) / 256, 256>>>(N);
    conv2_gather<<<(N + 255) / 256, 256>>>(N);
    mlp_kernel<<<(N + NT - 1) / NT, 256>>>(W1, b1, W2, b2, out, N);
}

// round 4
// speedup vs baseline: 1.2970x; 1.2970x over previous
#include <cuda_runtime.h>
#include <cuda_bf16.h>

// Problem constants (fixed shapes for this problem instance)
#define NMAX 100000
#define EMAX 6400000
#define HID  256
#define OUT  64
#define NT   32      // nodes per MLP tile
#define SCAN_BLKS ((NMAX + 1023) / 1024)   // 98

// Scratch (device globals: no allocation allowed in kernel_launch)
__device__ float g_xl[NMAX * 4];    // stride 4, 16B rows
__device__ float g_h1[NMAX * 16];   // stride 16, 64B rows
__device__ float g_h2[NMAX * 28];   // stride 28
__device__ int    g_count[NMAX];
__device__ int    g_off[NMAX + 1];
__device__ int    g_cursor[NMAX];
__device__ int    g_part[SCAN_BLKS];       // per-block sums
__device__ int    g_part_off[SCAN_BLKS];   // exclusive offsets of block sums
__device__ float4 g_edges[EMAX];    // {src(as int bits), k0, k1, k2} sorted by dst

// ---------------------------------------------------------------------------
// zero per-launch state (histogram counters)
// ---------------------------------------------------------------------------
__global__ void zero_kernel(int N) {
    int i = blockIdx.x * blockDim.x + threadIdx.x;
    if (i < N) g_count[i] = 0;
}

// ---------------------------------------------------------------------------
// xl[n,i] = sum_j gauges[n,j,i] * x[n,j]
// ---------------------------------------------------------------------------
__global__ void xl_kernel(const float* __restrict__ x,
                          const float* __restrict__ g, int N) {
    int n = blockIdx.x * blockDim.x + threadIdx.x;
    if (n >= N) return;
    float x0 = x[n * 3 + 0], x1 = x[n * 3 + 1], x2 = x[n * 3 + 2];
    const float* G = g + n * 9;
    float o0 = x0 * G[0] + x1 * G[3] + x2 * G[6];
    float o1 = x0 * G[1] + x1 * G[4] + x2 * G[7];
    float o2 = x0 * G[2] + x1 * G[5] + x2 * G[8];
    ((float4*)g_xl)[n] = make_float4(o0, o1, o2, 0.f);
}

// ---------------------------------------------------------------------------
// CSR build: histogram by dst
// ---------------------------------------------------------------------------
__global__ void hist_kernel(const int* __restrict__ ei, int E) {
    int e = blockIdx.x * blockDim.x + threadIdx.x;
    if (e >= E) return;
    atomicAdd(&g_count[ei[E + e]], 1);
}

// ---------------------------------------------------------------------------
// 3-phase parallel exclusive scan of g_count -> g_off / g_cursor
// ---------------------------------------------------------------------------
__global__ __launch_bounds__(1024) void scan_part(int N) {
    __shared__ int sm[1024];
    int t = threadIdx.x;
    int idx = blockIdx.x * 1024 + t;
    int v = (idx < N) ? g_count[idx] : 0;
    sm[t] = v;
    __syncthreads();
    for (int off = 512; off > 0; off >>= 1) {
        if (t < off) sm[t] += sm[t + off];
        __syncthreads();
    }
    if (t == 0) g_part[blockIdx.x] = sm[0];
}

__global__ void scan_top(int E, int N) {
    // single block of 128 threads scans SCAN_BLKS=98 partials
    __shared__ int sm[128];
    int t = threadIdx.x;
    int v = (t < SCAN_BLKS) ? g_part[t] : 0;
    sm[t] = v;
    __syncthreads();
    for (int off = 1; off < 128; off <<= 1) {
        int u = (t >= off) ? sm[t - off] : 0;
        __syncthreads();
        sm[t] += u;
        __syncthreads();
    }
    if (t < SCAN_BLKS) g_part_off[t] = sm[t] - v;   // exclusive
    if (t == 0) g_off[N] = E;
}

__global__ __launch_bounds__(1024) void scan_down(int N) {
    __shared__ int sm[1024];
    int t = threadIdx.x;
    int idx = blockIdx.x * 1024 + t;
    int v = (idx < N) ? g_count[idx] : 0;
    sm[t] = v;
    __syncthreads();
    // Hillis-Steele inclusive scan
    for (int off = 1; off < 1024; off <<= 1) {
        int u = (t >= off) ? sm[t - off] : 0;
        __syncthreads();
        sm[t] += u;
        __syncthreads();
    }
    if (idx < N) {
        int ex = sm[t] - v + g_part_off[blockIdx.x];
        g_off[idx]    = ex;
        g_cursor[idx] = ex;
    }
}

// ---------------------------------------------------------------------------
// Place edges into CSR slots: record = {src, k0, k1, k2}
// ---------------------------------------------------------------------------
__global__ void place_kernel(const int* __restrict__ ei,
                             const float* __restrict__ K, int E) {
    int e = blockIdx.x * blockDim.x + threadIdx.x;
    if (e >= E) return;
    int s = ei[e];
    int d = ei[E + e];
    float k0 = K[e], k1 = K[E + e], k2 = K[2 * E + e];
    int p = atomicAdd(&g_cursor[d], 1);
    g_edges[p] = make_float4(__int_as_float(s), k0, k1, k2);
}

// ---------------------------------------------------------------------------
// conv1 gather: h1[n, c*3+k] = sum_{e in csr(n)} K[k,e] * xl[src(e), c]
// one thread per node
// ---------------------------------------------------------------------------
__global__ void conv1_gather(int N) {
    int n = blockIdx.x * blockDim.x + threadIdx.x;
    if (n >= N) return;
    int b = g_off[n], en = g_off[n + 1];
    float a0 = 0, a1 = 0, a2 = 0, a3 = 0, a4 = 0, a5 = 0, a6 = 0, a7 = 0, a8 = 0;
    for (int i = b; i < en; i++) {
        float4 r = g_edges[i];
        int s = __float_as_int(r.x);
        float4 xv = ((const float4*)g_xl)[s];
        a0 += r.y * xv.x; a1 += r.z * xv.x; a2 += r.w * xv.x;
        a3 += r.y * xv.y; a4 += r.z * xv.y; a5 += r.w * xv.y;
        a6 += r.y * xv.z; a7 += r.z * xv.z; a8 += r.w * xv.z;
    }
    float4* row = (float4*)(g_h1 + n * 16);
    row[0] = make_float4(a0, a1, a2, a3);
    row[1] = make_float4(a4, a5, a6, a7);
    row[2] = make_float4(a8, 0.f, 0.f, 0.f);
}

// ---------------------------------------------------------------------------
// conv2 gather: h2[n, c*3+k] = sum_{e in csr(n)} K[k,e] * h1[src(e), c], c in [0,9)
// ---------------------------------------------------------------------------
__global__ void conv2_gather(int N) {
    int n = blockIdx.x * blockDim.x + threadIdx.x;
    if (n >= N) return;
    int b = g_off[n], en = g_off[n + 1];
    float acc[27];
#pragma unroll
    for (int i = 0; i < 27; i++) acc[i] = 0.f;
    for (int i = b; i < en; i++) {
        float4 r = g_edges[i];
        int s = __float_as_int(r.x);
        const float4* h1r = (const float4*)(g_h1 + s * 16);
        float4 A = h1r[0], B = h1r[1], C = h1r[2];
        float a[9] = {A.x, A.y, A.z, A.w, B.x, B.y, B.z, B.w, C.x};
#pragma unroll
        for (int c = 0; c < 9; c++) {
            acc[3 * c + 0] += r.y * a[c];
            acc[3 * c + 1] += r.z * a[c];
            acc[3 * c + 2] += r.w * a[c];
        }
    }
    float* row = g_h2 + n * 28;
#pragma unroll
    for (int q = 0; q < 6; q++)
        ((float4*)row)[q] = make_float4(acc[4 * q], acc[4 * q + 1], acc[4 * q + 2], acc[4 * q + 3]);
    ((float4*)row)[6] = make_float4(acc[24], acc[25], acc[26], 0.f);
}

// ---------------------------------------------------------------------------
// MLP: feats[39] = [xl(3) | h1(9) | h2(27)];  relu(feats@W1+b1)@W2+b2 -> out[64]
// ---------------------------------------------------------------------------
__global__ __launch_bounds__(256) void mlp_kernel(
    const float* __restrict__ W1, const float* __restrict__ b1,
    const float* __restrict__ W2, const float* __restrict__ b2,
    float* __restrict__ out, int N) {
    __shared__ float sh_feats[39 * NT];        // [j][n]
    __shared__ float sh_hmid[HID * 36];        // [h][n], stride 36

    int t = threadIdx.x;
    int node0 = blockIdx.x * NT;

    // --- load feats (transposed) ---
    {
        int n = t & (NT - 1);
        int node = node0 + n;
        bool valid = node < N;
        for (int j = t >> 5; j < 39; j += 8) {
            float v = 0.f;
            if (valid) {
                if (j < 3)       v = g_xl[node * 4 + j];
                else if (j < 12) v = g_h1[node * 16 + (j - 3)];
                else             v = g_h2[node * 28 + (j - 12)];
            }
            sh_feats[j * NT + n] = v;
        }
    }
    __syncthreads();

    // --- layer 1: hid[t][n] for n in [0,32) ---
    float acc[NT];
#pragma unroll
    for (int n = 0; n < NT; n++) acc[n] = 0.f;

    for (int j = 0; j < 39; j++) {
        float w = __ldg(W1 + j * HID + t);
        const float4* f4 = (const float4*)(sh_feats + j * NT);
#pragma unroll
        for (int q = 0; q < NT / 4; q++) {
            float4 f = f4[q];
            acc[4 * q + 0] += f.x * w;
            acc[4 * q + 1] += f.y * w;
            acc[4 * q + 2] += f.z * w;
            acc[4 * q + 3] += f.w * w;
        }
    }
    {
        float bb = __ldg(b1 + t);
        float* hr = sh_hmid + t * 36;
#pragma unroll
        for (int n = 0; n < NT; n++) hr[n] = fmaxf(acc[n] + bb, 0.f);
    }
    __syncthreads();

    // --- layer 2: 4 nodes x 2 outputs per thread ---
    int ng = t & 7;
    int og = t >> 3;
    int nb = 4 * ng;
    int o0 = 2 * og;
    float a00 = 0, a01 = 0, a10 = 0, a11 = 0, a20 = 0, a21 = 0, a30 = 0, a31 = 0;
#pragma unroll 4
    for (int h = 0; h < HID; h++) {
        float4 hm = *(const float4*)(sh_hmid + h * 36 + nb);
        float2 w = __ldg((const float2*)(W2 + h * OUT + o0));
        a00 += hm.x * w.x; a01 += hm.x * w.y;
        a10 += hm.y * w.x; a11 += hm.y * w.y;
        a20 += hm.z * w.x; a21 += hm.z * w.y;
        a30 += hm.w * w.x; a31 += hm.w * w.y;
    }
    float bo0 = __ldg(b2 + o0), bo1 = __ldg(b2 + o0 + 1);
    int node = node0 + nb;
    if (node + 0 < N) *(float2*)(out + (node + 0) * OUT + o0) = make_float2(a00 + bo0, a01 + bo1);
    if (node + 1 < N) *(float2*)(out + (node + 1) * OUT + o0) = make_float2(a10 + bo0, a11 + bo1);
    if (node + 2 < N) *(float2*)(out + (node + 2) * OUT + o0) = make_float2(a20 + bo0, a21 + bo1);
    if (node + 3 < N) *(float2*)(out + (node + 3) * OUT + o0) = make_float2(a30 + bo0, a31 + bo1);
}

// ---------------------------------------------------------------------------
// Launch: zero -> xl -> hist -> scan(x3) -> place -> conv1 -> conv2 -> mlp
// Inputs (metadata order): x, gauges, kernel_vals, W1, b1, W2, b2, edge_index
// ---------------------------------------------------------------------------
extern "C" void kernel_launch(void* const* d_in, const int* in_sizes, int n_in,
                              void* d_out, int out_size) {
    const float* x      = (const float*)d_in[0];
    const float* gauges = (const float*)d_in[1];
    const float* kvals  = (const float*)d_in[2];
    const float* W1     = (const float*)d_in[3];
    const float* b1     = (const float*)d_in[4];
    const float* W2     = (const float*)d_in[5];
    const float* b2     = (const float*)d_in[6];
    const int*   ei     = (const int*)d_in[7];   // int32 (JAX x64 disabled)
    float* out = (float*)d_out;

    int N = in_sizes[0] / 3;       // 100000
    int E = in_sizes[2] / 3;       // 6400000

    zero_kernel<<<(N + 255) / 256, 256>>>(N);
    xl_kernel<<<(N + 255) / 256, 256>>>(x, gauges, N);
    hist_kernel<<<(E + 255) / 256, 256>>>(ei, E);
    scan_part<<<SCAN_BLKS, 1024>>>(N);
    scan_top<<<1, 128>>>(E, N);
    scan_down<<<SCAN_BLKS, 1024>>>(N);
    place_kernel<<<(E + 255) / 256, 256>>>(ei, kvals, E);
    conv1_gather<<<(N + 255) / 256, 256>>>(N);
    conv2_gather<<<(N + 255) / 256, 256>>>(N);
    mlp_kernel<<<(N + NT - 1) / NT, 256>>>(W1, b1, W2, b2, out, N);
}

// round 5
// speedup vs baseline: 1.3090x; 1.0093x over previous
#include <cuda_runtime.h>
#include <cuda_bf16.h>

// Problem constants (fixed shapes for this problem instance)
#define NMAX 100000
#define EMAX 6400000
#define HID  256
#define OUT  64
#define NT   32      // nodes per MLP tile
#define SCAN_BLKS ((NMAX + 1023) / 1024)   // 98

// Scratch (device globals: no allocation allowed in kernel_launch)
__device__ float g_xl[NMAX * 4];    // stride 4, 16B rows
__device__ float g_h1[NMAX * 16];   // stride 16, 64B rows
__device__ float g_h2[NMAX * 28];   // stride 28
__device__ int    g_count[NMAX];
__device__ int    g_off[NMAX + 1];
__device__ int    g_cursor[NMAX];
__device__ int    g_part[SCAN_BLKS];       // per-block sums
__device__ int    g_part_off[SCAN_BLKS];   // exclusive offsets of block sums
__device__ float4 g_edges[EMAX];    // {src(as int bits), k0, k1, k2} sorted by dst

// packed f32x2 helpers (bit-identical to scalar fp32 math)
#define FMA_F32X2(acc, a, b) \
    asm("fma.rn.f32x2 %0, %1, %2, %0;" : "+l"(acc) : "l"(a), "l"(b))
#define PACK_DUP(out, s) \
    asm("mov.b64 %0, {%1, %1};" : "=l"(out) : "f"(s))
#define UNPACK2(lo, hi, in) \
    asm("mov.b64 {%0, %1}, %2;" : "=f"(lo), "=f"(hi) : "l"(in))

// ---------------------------------------------------------------------------
__global__ void zero_kernel(int N) {
    int i = blockIdx.x * blockDim.x + threadIdx.x;
    if (i < N) g_count[i] = 0;
}

// ---------------------------------------------------------------------------
// xl[n,i] = sum_j gauges[n,j,i] * x[n,j]
// ---------------------------------------------------------------------------
__global__ void xl_kernel(const float* __restrict__ x,
                          const float* __restrict__ g, int N) {
    int n = blockIdx.x * blockDim.x + threadIdx.x;
    if (n >= N) return;
    float x0 = x[n * 3 + 0], x1 = x[n * 3 + 1], x2 = x[n * 3 + 2];
    const float* G = g + n * 9;
    float o0 = x0 * G[0] + x1 * G[3] + x2 * G[6];
    float o1 = x0 * G[1] + x1 * G[4] + x2 * G[7];
    float o2 = x0 * G[2] + x1 * G[5] + x2 * G[8];
    ((float4*)g_xl)[n] = make_float4(o0, o1, o2, 0.f);
}

// ---------------------------------------------------------------------------
// CSR build: histogram by dst
// ---------------------------------------------------------------------------
__global__ void hist_kernel(const int* __restrict__ ei, int E) {
    int e = blockIdx.x * blockDim.x + threadIdx.x;
    if (e >= E) return;
    atomicAdd(&g_count[ei[E + e]], 1);
}

// ---------------------------------------------------------------------------
// 3-phase parallel exclusive scan of g_count -> g_off / g_cursor
// ---------------------------------------------------------------------------
__global__ __launch_bounds__(1024) void scan_part(int N) {
    __shared__ int sm[1024];
    int t = threadIdx.x;
    int idx = blockIdx.x * 1024 + t;
    int v = (idx < N) ? g_count[idx] : 0;
    sm[t] = v;
    __syncthreads();
    for (int off = 512; off > 0; off >>= 1) {
        if (t < off) sm[t] += sm[t + off];
        __syncthreads();
    }
    if (t == 0) g_part[blockIdx.x] = sm[0];
}

__global__ void scan_top(int E, int N) {
    __shared__ int sm[128];
    int t = threadIdx.x;
    int v = (t < SCAN_BLKS) ? g_part[t] : 0;
    sm[t] = v;
    __syncthreads();
    for (int off = 1; off < 128; off <<= 1) {
        int u = (t >= off) ? sm[t - off] : 0;
        __syncthreads();
        sm[t] += u;
        __syncthreads();
    }
    if (t < SCAN_BLKS) g_part_off[t] = sm[t] - v;   // exclusive
    if (t == 0) g_off[N] = E;
}

__global__ __launch_bounds__(1024) void scan_down(int N) {
    __shared__ int sm[1024];
    int t = threadIdx.x;
    int idx = blockIdx.x * 1024 + t;
    int v = (idx < N) ? g_count[idx] : 0;
    sm[t] = v;
    __syncthreads();
    for (int off = 1; off < 1024; off <<= 1) {
        int u = (t >= off) ? sm[t - off] : 0;
        __syncthreads();
        sm[t] += u;
        __syncthreads();
    }
    if (idx < N) {
        int ex = sm[t] - v + g_part_off[blockIdx.x];
        g_off[idx]    = ex;
        g_cursor[idx] = ex;
    }
}

// ---------------------------------------------------------------------------
// Place edges into CSR slots: record = {src, k0, k1, k2}
// ---------------------------------------------------------------------------
__global__ void place_kernel(const int* __restrict__ ei,
                             const float* __restrict__ K, int E) {
    int e = blockIdx.x * blockDim.x + threadIdx.x;
    if (e >= E) return;
    int s = ei[e];
    int d = ei[E + e];
    float k0 = K[e], k1 = K[E + e], k2 = K[2 * E + e];
    int p = atomicAdd(&g_cursor[d], 1);
    g_edges[p] = make_float4(__int_as_float(s), k0, k1, k2);
}

// ---------------------------------------------------------------------------
// conv1 gather: one thread per node
// ---------------------------------------------------------------------------
__global__ void conv1_gather(int N) {
    int n = blockIdx.x * blockDim.x + threadIdx.x;
    if (n >= N) return;
    int b = g_off[n], en = g_off[n + 1];
    float a0 = 0, a1 = 0, a2 = 0, a3 = 0, a4 = 0, a5 = 0, a6 = 0, a7 = 0, a8 = 0;
    for (int i = b; i < en; i++) {
        float4 r = g_edges[i];
        int s = __float_as_int(r.x);
        float4 xv = ((const float4*)g_xl)[s];
        a0 += r.y * xv.x; a1 += r.z * xv.x; a2 += r.w * xv.x;
        a3 += r.y * xv.y; a4 += r.z * xv.y; a5 += r.w * xv.y;
        a6 += r.y * xv.z; a7 += r.z * xv.z; a8 += r.w * xv.z;
    }
    float4* row = (float4*)(g_h1 + n * 16);
    row[0] = make_float4(a0, a1, a2, a3);
    row[1] = make_float4(a4, a5, a6, a7);
    row[2] = make_float4(a8, 0.f, 0.f, 0.f);
}

// ---------------------------------------------------------------------------
// conv2 gather
// ---------------------------------------------------------------------------
__global__ void conv2_gather(int N) {
    int n = blockIdx.x * blockDim.x + threadIdx.x;
    if (n >= N) return;
    int b = g_off[n], en = g_off[n + 1];
    float acc[27];
#pragma unroll
    for (int i = 0; i < 27; i++) acc[i] = 0.f;
    for (int i = b; i < en; i++) {
        float4 r = g_edges[i];
        int s = __float_as_int(r.x);
        const float4* h1r = (const float4*)(g_h1 + s * 16);
        float4 A = h1r[0], B = h1r[1], C = h1r[2];
        float a[9] = {A.x, A.y, A.z, A.w, B.x, B.y, B.z, B.w, C.x};
#pragma unroll
        for (int c = 0; c < 9; c++) {
            acc[3 * c + 0] += r.y * a[c];
            acc[3 * c + 1] += r.z * a[c];
            acc[3 * c + 2] += r.w * a[c];
        }
    }
    float* row = g_h2 + n * 28;
#pragma unroll
    for (int q = 0; q < 6; q++)
        ((float4*)row)[q] = make_float4(acc[4 * q], acc[4 * q + 1], acc[4 * q + 2], acc[4 * q + 3]);
    ((float4*)row)[6] = make_float4(acc[24], acc[25], acc[26], 0.f);
}

// ---------------------------------------------------------------------------
// MLP with packed f32x2 FFMA (FFMA2): halves fma-pipe instruction count.
// feats[39] = [xl(3) | h1(9) | h2(27)];  relu(feats@W1+b1)@W2+b2 -> out[64]
// ---------------------------------------------------------------------------
__global__ __launch_bounds__(256) void mlp_kernel(
    const float* __restrict__ W1, const float* __restrict__ b1,
    const float* __restrict__ W2, const float* __restrict__ b2,
    float* __restrict__ out, int N) {
    __shared__ float sh_feats[39 * NT];        // [j][n]
    __shared__ float sh_hmid[HID * 36];        // [h][n], stride 36 (8B-aligned pairs)

    int t = threadIdx.x;
    int node0 = blockIdx.x * NT;

    // --- load feats (transposed) ---
    {
        int n = t & (NT - 1);
        int node = node0 + n;
        bool valid = node < N;
        for (int j = t >> 5; j < 39; j += 8) {
            float v = 0.f;
            if (valid) {
                if (j < 3)       v = g_xl[node * 4 + j];
                else if (j < 12) v = g_h1[node * 16 + (j - 3)];
                else             v = g_h2[node * 28 + (j - 12)];
            }
            sh_feats[j * NT + n] = v;
        }
    }
    __syncthreads();

    // --- layer 1: hidden unit t for 32 nodes, 16 packed f32x2 accumulators ---
    unsigned long long acc2[NT / 2];
#pragma unroll
    for (int q = 0; q < NT / 2; q++) acc2[q] = 0ULL;

    for (int j = 0; j < 39; j++) {
        float w = __ldg(W1 + j * HID + t);
        unsigned long long wp; PACK_DUP(wp, w);
        const unsigned long long* f2 = (const unsigned long long*)(sh_feats + j * NT);
#pragma unroll
        for (int q = 0; q < NT / 2; q++) {
            unsigned long long f = f2[q];   // broadcast LDS.64
            FMA_F32X2(acc2[q], f, wp);
        }
    }
    {
        float bb = __ldg(b1 + t);
        float* hr = sh_hmid + t * 36;
#pragma unroll
        for (int q = 0; q < NT / 2; q++) {
            float lo, hi; UNPACK2(lo, hi, acc2[q]);
            hr[2 * q + 0] = fmaxf(lo + bb, 0.f);
            hr[2 * q + 1] = fmaxf(hi + bb, 0.f);
        }
    }
    __syncthreads();

    // --- layer 2: 4 nodes x 2 outputs per thread, packed over node pairs ---
    int ng = t & 7;           // node group: nodes 4*ng .. 4*ng+3
    int og = t >> 3;          // output pair: o = 2*og, 2*og+1
    int nb = 4 * ng;
    int o0 = 2 * og;
    // acc[pair p][output o] = {node(2p)·o, node(2p+1)·o}
    unsigned long long p0o0 = 0, p0o1 = 0, p1o0 = 0, p1o1 = 0;
#pragma unroll 4
    for (int h = 0; h < HID; h++) {
        const unsigned long long* hmp =
            (const unsigned long long*)(sh_hmid + h * 36 + nb);
        unsigned long long hm01 = hmp[0];   // {hm[n0], hm[n1]}
        unsigned long long hm23 = hmp[1];   // {hm[n2], hm[n3]}
        float2 w = __ldg((const float2*)(W2 + h * OUT + o0));
        unsigned long long w0p, w1p;
        PACK_DUP(w0p, w.x);
        PACK_DUP(w1p, w.y);
        FMA_F32X2(p0o0, hm01, w0p);
        FMA_F32X2(p0o1, hm01, w1p);
        FMA_F32X2(p1o0, hm23, w0p);
        FMA_F32X2(p1o1, hm23, w1p);
    }
    float bo0 = __ldg(b2 + o0), bo1 = __ldg(b2 + o0 + 1);
    float n0o0, n1o0, n2o0, n3o0, n0o1, n1o1, n2o1, n3o1;
    UNPACK2(n0o0, n1o0, p0o0);
    UNPACK2(n0o1, n1o1, p0o1);
    UNPACK2(n2o0, n3o0, p1o0);
    UNPACK2(n2o1, n3o1, p1o1);
    int node = node0 + nb;
    if (node + 0 < N) *(float2*)(out + (node + 0) * OUT + o0) = make_float2(n0o0 + bo0, n0o1 + bo1);
    if (node + 1 < N) *(float2*)(out + (node + 1) * OUT + o0) = make_float2(n1o0 + bo0, n1o1 + bo1);
    if (node + 2 < N) *(float2*)(out + (node + 2) * OUT + o0) = make_float2(n2o0 + bo0, n2o1 + bo1);
    if (node + 3 < N) *(float2*)(out + (node + 3) * OUT + o0) = make_float2(n3o0 + bo0, n3o1 + bo1);
}

// ---------------------------------------------------------------------------
// Launch: zero -> xl -> hist -> scan(x3) -> place -> conv1 -> conv2 -> mlp
// Inputs (metadata order): x, gauges, kernel_vals, W1, b1, W2, b2, edge_index
// ---------------------------------------------------------------------------
extern "C" void kernel_launch(void* const* d_in, const int* in_sizes, int n_in,
                              void* d_out, int out_size) {
    const float* x      = (const float*)d_in[0];
    const float* gauges = (const float*)d_in[1];
    const float* kvals  = (const float*)d_in[2];
    const float* W1     = (const float*)d_in[3];
    const float* b1     = (const float*)d_in[4];
    const float* W2     = (const float*)d_in[5];
    const float* b2     = (const float*)d_in[6];
    const int*   ei     = (const int*)d_in[7];   // int32 (JAX x64 disabled)
    float* out = (float*)d_out;

    int N = in_sizes[0] / 3;       // 100000
    int E = in_sizes[2] / 3;       // 6400000

    zero_kernel<<<(N + 255) / 256, 256>>>(N);
    xl_kernel<<<(N + 255) / 256, 256>>>(x, gauges, N);
    hist_kernel<<<(E + 255) / 256, 256>>>(ei, E);
    scan_part<<<SCAN_BLKS, 1024>>>(N);
    scan_top<<<1, 128>>>(E, N);
    scan_down<<<SCAN_BLKS, 1024>>>(N);
    place_kernel<<<(E + 255) / 256, 256>>>(ei, kvals, E);
    conv1_gather<<<(N + 255) / 256, 256>>>(N);
    conv2_gather<<<(N + 255) / 256, 256>>>(N);
    mlp_kernel<<<(N + NT - 1) / NT, 256>>>(W1, b1, W2, b2, out, N);
}